// round 1
// baseline (speedup 1.0000x reference)
#include <cuda_runtime.h>
#include <cuda_bf16.h>
#include <math.h>

// Problem constants (fixed by the dataset)
#define NN 50000
#define NE 800000
#define DIN 512
#define C1 256
#define C2 128
#define HID 64

// ---------------- scratch (device globals; no allocations allowed) ----------
__device__ float g_app_s[NN];
__device__ float g_app_d[NN];
__device__ float g_geo_s[NN];
__device__ float g_geo_d[NN];
__device__ float g_ew1[NE];
__device__ float g_deg1[NN];   // deg, then overwritten with dinv
__device__ float g_ms[NN];
__device__ float g_md[NN];
__device__ float g_ew2[NE];
__device__ float g_deg2[NN];
__device__ float g_h1[(size_t)NN * C1];
__device__ float g_out1[(size_t)NN * C1];
__device__ float g_h2[(size_t)NN * C2];
__device__ float g_out2[(size_t)NN * C2];
__device__ float g_proj[(size_t)NN * HID];

// ---------------- helpers ----------------------------------------------------
__device__ __forceinline__ void redAdd4(float* addr, float4 v) {
    asm volatile("red.global.add.v4.f32 [%0], {%1,%2,%3,%4};"
                 :: "l"(addr), "f"(v.x), "f"(v.y), "f"(v.z), "f"(v.w)
                 : "memory");
}

__device__ __forceinline__ float warpReduceSum(float v) {
#pragma unroll
    for (int off = 16; off > 0; off >>= 1)
        v += __shfl_down_sync(0xFFFFFFFFu, v, off);
    return v;
}

// ---------------- kernels ----------------------------------------------------

__global__ void k_zero_deg() {
    int i = blockIdx.x * blockDim.x + threadIdx.x;
    if (i < NN) { g_deg1[i] = 0.f; g_deg2[i] = 0.f; }
}

// app_s/app_d (dot of x row with W_app halves) + geo_s/geo_d. Warp per node.
__global__ void k_node_dots(const float* __restrict__ x,
                            const float* __restrict__ coords,
                            const float* __restrict__ Wapp,
                            const float* __restrict__ Wgeom) {
    int gw = (blockIdx.x * blockDim.x + threadIdx.x) >> 5;
    int lane = threadIdx.x & 31;
    if (gw >= NN) return;
    const float4* row = (const float4*)(x + (size_t)gw * DIN);
    const float4* wa = (const float4*)Wapp;
    float s = 0.f, d = 0.f;
#pragma unroll
    for (int i = 0; i < 4; i++) {
        int idx = lane + 32 * i;
        float4 v = row[idx];
        float4 ws = wa[idx];
        float4 wd = wa[idx + 128];
        s += v.x * ws.x + v.y * ws.y + v.z * ws.z + v.w * ws.w;
        d += v.x * wd.x + v.y * wd.y + v.z * wd.z + v.w * wd.w;
    }
    s = warpReduceSum(s);
    d = warpReduceSum(d);
    if (lane == 0) {
        g_app_s[gw] = s;
        g_app_d[gw] = d;
        float4 c = ((const float4*)coords)[gw];
        g_geo_s[gw] = c.x * Wgeom[0] + c.y * Wgeom[1] + c.z * Wgeom[2] + c.w * Wgeom[3];
        g_geo_d[gw] = c.x * Wgeom[4] + c.y * Wgeom[5] + c.z * Wgeom[6] + c.w * Wgeom[7];
    }
}

// edge weights for GCN1 + degree accumulation
__global__ void k_edge1(const int* __restrict__ src, const int* __restrict__ dst,
                        const float* __restrict__ Waff,
                        const float* __restrict__ bapp,
                        const float* __restrict__ bgeom,
                        const float* __restrict__ baff) {
    int e = blockIdx.x * blockDim.x + threadIdx.x;
    if (e >= NE) return;
    int s = src[e], d = dst[e];
    float x1 = fmaxf(g_app_s[s] + g_app_d[d] + bapp[0], 0.f);
    float x2 = fmaxf(g_geo_s[s] + g_geo_d[d] + bgeom[0], 0.f);
    float ew = fmaxf(x1 * Waff[0] + x2 * Waff[1] + baff[0], 0.f);
    g_ew1[e] = ew;
    if (ew != 0.f) atomicAdd(&g_deg1[d], ew);
}

__global__ void k_dinv1() {
    int i = blockIdx.x * blockDim.x + threadIdx.x;
    if (i < NN) g_deg1[i] = rsqrtf(g_deg1[i] + 1.0f);  // +1 self-loop; deg>=1
}

__global__ void k_dinv2() {
    int i = blockIdx.x * blockDim.x + threadIdx.x;
    if (i < NN) g_deg2[i] = rsqrtf(g_deg2[i] + 1.0f);
}

// classic shared-memory SGEMM: C[M,N] = A[M,K] @ B[K,N] (row-major)
template <int BM, int BN, int BK, int TM, int TN>
__global__ void k_sgemm(const float* __restrict__ A, const float* __restrict__ B,
                        float* __restrict__ C, int M, int N, int K) {
    __shared__ float As[BK][BM];
    __shared__ float Bs[BK][BN];
    const int tid = threadIdx.x;                // 256 threads
    const int tx = tid % (BN / TN);             // 0..15
    const int ty = tid / (BN / TN);             // 0..15
    const int row0 = blockIdx.x * BM;
    const int col0 = blockIdx.y * BN;

    float acc[TM][TN];
#pragma unroll
    for (int i = 0; i < TM; i++)
#pragma unroll
        for (int j = 0; j < TN; j++) acc[i][j] = 0.f;

    const int a_m = tid >> 1;            // 0..127
    const int a_k = (tid & 1) * 8;       // 0 or 8
    const int b_k = tid >> 4;            // 0..15
    const int b_n = (tid & 15) * 4;      // 0..60

    for (int k0 = 0; k0 < K; k0 += BK) {
        int arow = row0 + a_m;
        if (arow < M) {
            float4 v0 = *(const float4*)(A + (size_t)arow * K + k0 + a_k);
            float4 v1 = *(const float4*)(A + (size_t)arow * K + k0 + a_k + 4);
            As[a_k + 0][a_m] = v0.x; As[a_k + 1][a_m] = v0.y;
            As[a_k + 2][a_m] = v0.z; As[a_k + 3][a_m] = v0.w;
            As[a_k + 4][a_m] = v1.x; As[a_k + 5][a_m] = v1.y;
            As[a_k + 6][a_m] = v1.z; As[a_k + 7][a_m] = v1.w;
        } else {
#pragma unroll
            for (int i = 0; i < 8; i++) As[a_k + i][a_m] = 0.f;
        }
        *(float4*)&Bs[b_k][b_n] = *(const float4*)(B + (size_t)(k0 + b_k) * N + col0 + b_n);
        __syncthreads();

#pragma unroll
        for (int k = 0; k < BK; k++) {
            float ra[TM];
            float4 ra0 = *(const float4*)&As[k][ty * TM];
            float4 ra1 = *(const float4*)&As[k][ty * TM + 4];
            ra[0] = ra0.x; ra[1] = ra0.y; ra[2] = ra0.z; ra[3] = ra0.w;
            ra[4] = ra1.x; ra[5] = ra1.y; ra[6] = ra1.z; ra[7] = ra1.w;
            float4 rb = *(const float4*)&Bs[k][tx * TN];
            float rbv[TN] = {rb.x, rb.y, rb.z, rb.w};
#pragma unroll
            for (int i = 0; i < TM; i++)
#pragma unroll
                for (int j = 0; j < TN; j++) acc[i][j] = fmaf(ra[i], rbv[j], acc[i][j]);
        }
        __syncthreads();
    }

#pragma unroll
    for (int i = 0; i < TM; i++) {
        int r = row0 + ty * TM + i;
        if (r < M) {
            float4 v = make_float4(acc[i][0], acc[i][1], acc[i][2], acc[i][3]);
            *(float4*)(C + (size_t)r * N + col0 + tx * TN) = v;
        }
    }
}

// out1 := dinv^2 * h1 (self-loop term)
__global__ void k_init_out1() {
    int t = blockIdx.x * blockDim.x + threadIdx.x;   // float4 index
    if (t >= NN * (C1 / 4)) return;
    int node = t / (C1 / 4);
    float di = g_deg1[node];
    float c = di * di;
    float4 v = ((const float4*)g_h1)[t];
    ((float4*)g_out1)[t] = make_float4(c * v.x, c * v.y, c * v.z, c * v.w);
}

// per-edge scatter-add (256-dim), warp per edge, float4 red atomics
__global__ void k_scatter1(const int* __restrict__ src, const int* __restrict__ dst) {
    int e = (blockIdx.x * blockDim.x + threadIdx.x) >> 5;
    if (e >= NE) return;
    float ew = g_ew1[e];
    if (ew == 0.f) return;
    int lane = threadIdx.x & 31;
    int s = src[e], d = dst[e];
    float coef = g_deg1[s] * ew * g_deg1[d];
    const float4* hs = (const float4*)(g_h1 + (size_t)s * C1);
    float* od = g_out1 + (size_t)d * C1;
#pragma unroll
    for (int i = 0; i < 2; i++) {
        int idx = lane + 32 * i;
        float4 v = hs[idx];
        redAdd4(od + idx * 4, make_float4(coef * v.x, coef * v.y, coef * v.z, coef * v.w));
    }
}

__global__ void k_bias_relu1(const float* __restrict__ bc1) {
    int t = blockIdx.x * blockDim.x + threadIdx.x;
    if (t >= NN * (C1 / 4)) return;
    int c4 = t & (C1 / 4 - 1);
    float4 b = ((const float4*)bc1)[c4];
    float4 v = ((float4*)g_out1)[t];
    v.x = fmaxf(v.x + b.x, 0.f);
    v.y = fmaxf(v.y + b.y, 0.f);
    v.z = fmaxf(v.z + b.z, 0.f);
    v.w = fmaxf(v.w + b.w, 0.f);
    ((float4*)g_out1)[t] = v;
}

// m_s / m_d dots over out1, warp per node
__global__ void k_mdots(const float* __restrict__ Wm1) {
    int gw = (blockIdx.x * blockDim.x + threadIdx.x) >> 5;
    int lane = threadIdx.x & 31;
    if (gw >= NN) return;
    const float4* row = (const float4*)(g_out1 + (size_t)gw * C1);
    const float4* wm = (const float4*)Wm1;
    float s = 0.f, d = 0.f;
#pragma unroll
    for (int i = 0; i < 2; i++) {
        int idx = lane + 32 * i;
        float4 v = row[idx];
        float4 ws = wm[idx];
        float4 wd = wm[idx + 64];
        s += v.x * ws.x + v.y * ws.y + v.z * ws.z + v.w * ws.w;
        d += v.x * wd.x + v.y * wd.y + v.z * wd.z + v.w * wd.w;
    }
    s = warpReduceSum(s);
    d = warpReduceSum(d);
    if (lane == 0) { g_ms[gw] = s; g_md[gw] = d; }
}

__global__ void k_edge2(const int* __restrict__ src, const int* __restrict__ dst,
                        const float* __restrict__ bm1) {
    int e = blockIdx.x * blockDim.x + threadIdx.x;
    if (e >= NE) return;
    int s = src[e], d = dst[e];
    float ea = fmaxf(g_ms[s] + g_md[d] + bm1[0], 0.f);
    g_ew2[e] = ea;
    if (ea != 0.f) atomicAdd(&g_deg2[d], ea);
}

__global__ void k_init_out2() {
    int t = blockIdx.x * blockDim.x + threadIdx.x;
    if (t >= NN * (C2 / 4)) return;
    int node = t / (C2 / 4);
    float di = g_deg2[node];
    float c = di * di;
    float4 v = ((const float4*)g_h2)[t];
    ((float4*)g_out2)[t] = make_float4(c * v.x, c * v.y, c * v.z, c * v.w);
}

__global__ void k_scatter2(const int* __restrict__ src, const int* __restrict__ dst) {
    int e = (blockIdx.x * blockDim.x + threadIdx.x) >> 5;
    if (e >= NE) return;
    float ew = g_ew2[e];
    if (ew == 0.f) return;
    int lane = threadIdx.x & 31;
    int s = src[e], d = dst[e];
    float coef = g_deg2[s] * ew * g_deg2[d];
    const float4* hs = (const float4*)(g_h2 + (size_t)s * C2);
    float* od = g_out2 + (size_t)d * C2;
    float4 v = hs[lane];
    redAdd4(od + lane * 4, make_float4(coef * v.x, coef * v.y, coef * v.z, coef * v.w));
}

// proj = out2 @ W_f1  ([N,128]x[128,64]); b_c2 cancels in the pairwise diff so skipped
__global__ void k_proj(const float* __restrict__ Wf1) {
    __shared__ float W1s[C2 * HID];
    for (int i = threadIdx.x; i < C2 * HID; i += blockDim.x) W1s[i] = Wf1[i];
    __syncthreads();
    int t = blockIdx.x * blockDim.x + threadIdx.x;
    int node = t >> 6;
    int j = t & 63;
    if (node >= NN) return;
    const float* row = g_out2 + (size_t)node * C2;
    float acc = 0.f;
#pragma unroll 8
    for (int k = 0; k < C2; k++) acc = fmaf(row[k], W1s[k * HID + j], acc);
    g_proj[(size_t)node * HID + j] = acc;
}

// final: sigmoid( relu(proj[a]-proj[b]+b_f1) @ W_f2 + b_f2 ), warp per edge
__global__ void k_final(const int* __restrict__ ea, const int* __restrict__ eb,
                        const float* __restrict__ bf1, const float* __restrict__ Wf2,
                        const float* __restrict__ bf2, float* __restrict__ out) {
    int e = (blockIdx.x * blockDim.x + threadIdx.x) >> 5;
    if (e >= NE) return;
    int lane = threadIdx.x & 31;
    int a = ea[e], b = eb[e];
    const float* pa = g_proj + (size_t)a * HID;
    const float* pb = g_proj + (size_t)b * HID;
    float acc = 0.f;
#pragma unroll
    for (int i = 0; i < 2; i++) {
        int j = lane + 32 * i;
        float v = fmaxf(pa[j] - pb[j] + bf1[j], 0.f);
        acc = fmaf(v, Wf2[j], acc);
    }
    acc = warpReduceSum(acc);
    if (lane == 0) {
        float z = acc + bf2[0];
        out[e] = 1.f / (1.f + expf(-z));
    }
}

// ---------------- launcher ---------------------------------------------------
extern "C" void kernel_launch(void* const* d_in, const int* in_sizes, int n_in,
                              void* d_out, int out_size) {
    const float* x      = (const float*)d_in[0];
    const float* coords = (const float*)d_in[1];
    const float* W_app  = (const float*)d_in[2];
    const float* b_app  = (const float*)d_in[3];
    const float* W_geom = (const float*)d_in[4];
    const float* b_geom = (const float*)d_in[5];
    const float* W_aff  = (const float*)d_in[6];
    const float* b_aff  = (const float*)d_in[7];
    const float* W_c1   = (const float*)d_in[8];
    // d_in[9] = b_c1
    const float* b_c1   = (const float*)d_in[9];
    const float* W_m1   = (const float*)d_in[10];
    const float* b_m1   = (const float*)d_in[11];
    const float* W_c2   = (const float*)d_in[12];
    // d_in[13] = b_c2 (cancels in pairwise diff; unused)
    const float* W_f1   = (const float*)d_in[14];
    const float* b_f1   = (const float*)d_in[15];
    const float* W_f2   = (const float*)d_in[16];
    const float* b_f2   = (const float*)d_in[17];
    const int* ei  = (const int*)d_in[18];
    const int* ei2 = (const int*)d_in[19];
    const int* src = ei;
    const int* dst = ei + NE;

    float *h1p, *out1p, *h2p;
    cudaGetSymbolAddress((void**)&h1p, g_h1);
    cudaGetSymbolAddress((void**)&out1p, g_out1);
    cudaGetSymbolAddress((void**)&h2p, g_h2);

    k_zero_deg<<<(NN + 255) / 256, 256>>>();
    k_node_dots<<<(NN + 7) / 8, 256>>>(x, coords, W_app, W_geom);
    k_edge1<<<(NE + 255) / 256, 256>>>(src, dst, W_aff, b_app, b_geom, b_aff);
    k_dinv1<<<(NN + 255) / 256, 256>>>();
    k_sgemm<128, 64, 16, 8, 4><<<dim3((NN + 127) / 128, C1 / 64), 256>>>(
        x, W_c1, h1p, NN, C1, DIN);
    k_init_out1<<<(NN * (C1 / 4) + 255) / 256, 256>>>();
    k_scatter1<<<(NE * 32 + 255) / 256, 256>>>(src, dst);
    k_bias_relu1<<<(NN * (C1 / 4) + 255) / 256, 256>>>(b_c1);
    k_mdots<<<(NN + 7) / 8, 256>>>(W_m1);
    k_edge2<<<(NE + 255) / 256, 256>>>(src, dst, b_m1);
    k_dinv2<<<(NN + 255) / 256, 256>>>();
    k_sgemm<128, 64, 16, 8, 4><<<dim3((NN + 127) / 128, C2 / 64), 256>>>(
        out1p, W_c2, h2p, NN, C2, C1);
    k_init_out2<<<(NN * (C2 / 4) + 255) / 256, 256>>>();
    k_scatter2<<<(NE * 32 + 255) / 256, 256>>>(src, dst);
    k_proj<<<(NN * HID + 511) / 512, 512>>>(W_f1);
    k_final<<<(NE * 32 + 255) / 256, 256>>>(ei2, ei2 + NE, b_f1, W_f2, b_f2,
                                            (float*)d_out);
}

// round 6
// speedup vs baseline: 1.4316x; 1.4316x over previous
#include <cuda_runtime.h>
#include <cuda_bf16.h>
#include <math.h>
#include <stdint.h>
#include <stddef.h>

// Problem constants (fixed by the dataset)
#define NN 50000
#define NE 800000
#define DIN 512
#define C1 256
#define C2 128
#define HID 64

// ---------------- scratch (device globals; no allocations allowed) ----------
__device__ float g_app_s[NN];
__device__ float g_app_d[NN];
__device__ float g_geo_s[NN];
__device__ float g_geo_d[NN];
__device__ float g_ew1[NE];
__device__ float g_deg1[NN];   // deg, then overwritten with dinv
__device__ float g_ms[NN];
__device__ float g_md[NN];
__device__ float g_ew2[NE];
__device__ float g_deg2[NN];
__device__ float g_h1[(size_t)NN * C1];
__device__ float g_out1[(size_t)NN * C1];
__device__ float g_h2[(size_t)NN * C2];
__device__ float g_out2[(size_t)NN * C2];
__device__ float g_proj[(size_t)NN * HID];

// ---------------- helpers ----------------------------------------------------
__device__ __forceinline__ void redAdd4(float* addr, float4 v) {
    asm volatile("red.global.add.v4.f32 [%0], {%1,%2,%3,%4};"
                 :: "l"(addr), "f"(v.x), "f"(v.y), "f"(v.z), "f"(v.w)
                 : "memory");
}

__device__ __forceinline__ float warpReduceSum(float v) {
#pragma unroll
    for (int off = 16; off > 0; off >>= 1)
        v += __shfl_down_sync(0xFFFFFFFFu, v, off);
    return v;
}

__device__ __forceinline__ uint32_t f2tf(float f) {
    uint32_t r;
    asm("cvt.rna.tf32.f32 %0, %1;" : "=r"(r) : "f"(f));
    return r;
}

__device__ __forceinline__ void mma_tf32(float* c, const uint32_t* a, const uint32_t* b) {
    asm volatile(
        "mma.sync.aligned.m16n8k8.row.col.f32.tf32.tf32.f32 "
        "{%0,%1,%2,%3}, {%4,%5,%6,%7}, {%8,%9}, {%0,%1,%2,%3};"
        : "+f"(c[0]), "+f"(c[1]), "+f"(c[2]), "+f"(c[3])
        : "r"(a[0]), "r"(a[1]), "r"(a[2]), "r"(a[3]), "r"(b[0]), "r"(b[1]));
}

#define CP_ASYNC16(dst, src) \
    asm volatile("cp.async.cg.shared.global [%0], [%1], 16;" :: "r"(dst), "l"(src))
#define CP_COMMIT asm volatile("cp.async.commit_group;")
template <int N>
__device__ __forceinline__ void cp_wait() {
    asm volatile("cp.async.wait_group %0;" :: "n"(N));
}

// ---------------- kernels ----------------------------------------------------

__global__ void k_zero_deg() {
    int i = blockIdx.x * blockDim.x + threadIdx.x;
    if (i < NN) { g_deg1[i] = 0.f; g_deg2[i] = 0.f; }
}

// app_s/app_d (dot of x row with W_app halves) + geo_s/geo_d. Warp per node.
__global__ void k_node_dots(const float* __restrict__ x,
                            const float* __restrict__ coords,
                            const float* __restrict__ Wapp,
                            const float* __restrict__ Wgeom) {
    int gw = (blockIdx.x * blockDim.x + threadIdx.x) >> 5;
    int lane = threadIdx.x & 31;
    if (gw >= NN) return;
    const float4* row = (const float4*)(x + (size_t)gw * DIN);
    const float4* wa = (const float4*)Wapp;
    float s = 0.f, d = 0.f;
#pragma unroll
    for (int i = 0; i < 4; i++) {
        int idx = lane + 32 * i;
        float4 v = row[idx];
        float4 ws = wa[idx];
        float4 wd = wa[idx + 128];
        s += v.x * ws.x + v.y * ws.y + v.z * ws.z + v.w * ws.w;
        d += v.x * wd.x + v.y * wd.y + v.z * wd.z + v.w * wd.w;
    }
    s = warpReduceSum(s);
    d = warpReduceSum(d);
    if (lane == 0) {
        g_app_s[gw] = s;
        g_app_d[gw] = d;
        float4 c = ((const float4*)coords)[gw];
        g_geo_s[gw] = c.x * Wgeom[0] + c.y * Wgeom[1] + c.z * Wgeom[2] + c.w * Wgeom[3];
        g_geo_d[gw] = c.x * Wgeom[4] + c.y * Wgeom[5] + c.z * Wgeom[6] + c.w * Wgeom[7];
    }
}

// edge weights for GCN1 + degree accumulation
__global__ void k_edge1(const int* __restrict__ src, const int* __restrict__ dst,
                        const float* __restrict__ Waff,
                        const float* __restrict__ bapp,
                        const float* __restrict__ bgeom,
                        const float* __restrict__ baff) {
    int e = blockIdx.x * blockDim.x + threadIdx.x;
    if (e >= NE) return;
    int s = src[e], d = dst[e];
    float x1 = fmaxf(g_app_s[s] + g_app_d[d] + bapp[0], 0.f);
    float x2 = fmaxf(g_geo_s[s] + g_geo_d[d] + bgeom[0], 0.f);
    float ew = fmaxf(x1 * Waff[0] + x2 * Waff[1] + baff[0], 0.f);
    g_ew1[e] = ew;
    if (ew != 0.f) atomicAdd(&g_deg1[d], ew);
}

__global__ void k_dinv1() {
    int i = blockIdx.x * blockDim.x + threadIdx.x;
    if (i < NN) g_deg1[i] = rsqrtf(g_deg1[i] + 1.0f);  // +1 self-loop; deg>=1
}

__global__ void k_dinv2() {
    int i = blockIdx.x * blockDim.x + threadIdx.x;
    if (i < NN) g_deg2[i] = rsqrtf(g_deg2[i] + 1.0f);
}

// ---------------- TF32 tensor-core GEMM --------------------------------------
// C[M,N] = A[M,K] @ B[K,N], row-major. Block tile 128x128xBK16, 8 warps,
// warp tile 32x64 via m16n8k8 (2 m-tiles x 8 n-tiles). cp.async double buffer.
// As stride 20 / Bs stride 136: bank-conflict-free fragment reads.
// Tail M handling: A source row is clamped to a valid row (each A row feeds
// only its own C row, and OOB C rows are never stored), so all cp.async are
// plain full-16B copies from in-bounds addresses.
#define GA_BM 128
#define GA_BK 16
#define GA_AS_STRIDE 20
#define GA_BS_STRIDE 136

__global__ __launch_bounds__(256) void k_gemm_tf32(
    const float* __restrict__ A, const float* __restrict__ B,
    float* __restrict__ C, int M, int N, int K) {
    __shared__ float As[2][GA_BM * GA_AS_STRIDE];
    __shared__ float Bs[2][GA_BK * GA_BS_STRIDE];

    const int tid = threadIdx.x;
    const int lane = tid & 31;
    const int wid = tid >> 5;
    const int wm = wid & 3;       // 0..3  (rows)
    const int wn = wid >> 2;      // 0..1  (cols)
    const int grp = lane >> 2;    // 0..7
    const int qid = lane & 3;     // 0..3

    const int row0 = blockIdx.x * GA_BM;
    const int col0 = blockIdx.y * 128;

    // staging coordinates
    const int ar0 = tid >> 2;               // 0..63
    const int ac = (tid & 3) * 4;           // 0,4,8,12
    const int br0 = tid >> 5;               // 0..7
    const int bc = (tid & 31) * 4;          // 0..124

    // clamped source rows (always in-bounds)
    const int arow_g0 = min(row0 + ar0, M - 1);
    const int arow_g1 = min(row0 + ar0 + 64, M - 1);

    float acc[2][8][4];
#pragma unroll
    for (int mt = 0; mt < 2; mt++)
#pragma unroll
        for (int nt = 0; nt < 8; nt++)
#pragma unroll
            for (int i = 0; i < 4; i++) acc[mt][nt][i] = 0.f;

    auto load_tile = [&](int buf, int k0) {
        uint32_t a_s0 = (uint32_t)__cvta_generic_to_shared(
            &As[buf][ar0 * GA_AS_STRIDE + ac]);
        uint32_t a_s1 = (uint32_t)__cvta_generic_to_shared(
            &As[buf][(ar0 + 64) * GA_AS_STRIDE + ac]);
        const float* a_g0 = A + (size_t)arow_g0 * K + k0 + ac;
        const float* a_g1 = A + (size_t)arow_g1 * K + k0 + ac;
        CP_ASYNC16(a_s0, a_g0);
        CP_ASYNC16(a_s1, a_g1);
        uint32_t b_s0 = (uint32_t)__cvta_generic_to_shared(
            &Bs[buf][br0 * GA_BS_STRIDE + bc]);
        uint32_t b_s1 = (uint32_t)__cvta_generic_to_shared(
            &Bs[buf][(br0 + 8) * GA_BS_STRIDE + bc]);
        const float* b_g0 = B + (size_t)(k0 + br0) * N + col0 + bc;
        const float* b_g1 = B + (size_t)(k0 + br0 + 8) * N + col0 + bc;
        CP_ASYNC16(b_s0, b_g0);
        CP_ASYNC16(b_s1, b_g1);
    };

    const int ntiles = K / GA_BK;
    load_tile(0, 0);
    CP_COMMIT;

    int buf = 0;
    const int arow_base = wm * 32 + grp;
    const int bcol_base = wn * 64 + grp;

    for (int t = 0; t < ntiles; t++) {
        if (t + 1 < ntiles) {
            load_tile(buf ^ 1, (t + 1) * GA_BK);
            CP_COMMIT;
            cp_wait<1>();
        } else {
            cp_wait<0>();
        }
        __syncthreads();

        const float* as = As[buf];
        const float* bs = Bs[buf];
#pragma unroll
        for (int ks = 0; ks < 2; ks++) {
            const int kk = ks * 8 + qid;
            uint32_t a[2][4];
#pragma unroll
            for (int mt = 0; mt < 2; mt++) {
                const float* ap = as + (arow_base + mt * 16) * GA_AS_STRIDE + kk;
                a[mt][0] = f2tf(ap[0]);
                a[mt][1] = f2tf(ap[8 * GA_AS_STRIDE]);
                a[mt][2] = f2tf(ap[4]);
                a[mt][3] = f2tf(ap[8 * GA_AS_STRIDE + 4]);
            }
            const float* bp = bs + kk * GA_BS_STRIDE + bcol_base;
#pragma unroll
            for (int nt = 0; nt < 8; nt++) {
                uint32_t b[2];
                b[0] = f2tf(bp[nt * 8]);
                b[1] = f2tf(bp[4 * GA_BS_STRIDE + nt * 8]);
                mma_tf32(acc[0][nt], a[0], b);
                mma_tf32(acc[1][nt], a[1], b);
            }
        }
        __syncthreads();
        buf ^= 1;
    }

    // epilogue
#pragma unroll
    for (int mt = 0; mt < 2; mt++) {
#pragma unroll
        for (int nt = 0; nt < 8; nt++) {
            int r = row0 + wm * 32 + mt * 16 + grp;
            int c = col0 + wn * 64 + nt * 8 + qid * 2;
            if (r < M) {
                float2 v = make_float2(acc[mt][nt][0], acc[mt][nt][1]);
                *(float2*)(C + (size_t)r * N + c) = v;
            }
            if (r + 8 < M) {
                float2 v = make_float2(acc[mt][nt][2], acc[mt][nt][3]);
                *(float2*)(C + (size_t)(r + 8) * N + c) = v;
            }
        }
    }
}

// out1 := dinv^2 * h1 (self-loop term)
__global__ void k_init_out1() {
    int t = blockIdx.x * blockDim.x + threadIdx.x;   // float4 index
    if (t >= NN * (C1 / 4)) return;
    int node = t / (C1 / 4);
    float di = g_deg1[node];
    float c = di * di;
    float4 v = ((const float4*)g_h1)[t];
    ((float4*)g_out1)[t] = make_float4(c * v.x, c * v.y, c * v.z, c * v.w);
}

// per-edge scatter-add (256-dim), warp per edge, float4 red atomics
__global__ void k_scatter1(const int* __restrict__ src, const int* __restrict__ dst) {
    int e = (blockIdx.x * blockDim.x + threadIdx.x) >> 5;
    if (e >= NE) return;
    float ew = g_ew1[e];
    if (ew == 0.f) return;
    int lane = threadIdx.x & 31;
    int s = src[e], d = dst[e];
    float coef = g_deg1[s] * ew * g_deg1[d];
    const float4* hs = (const float4*)(g_h1 + (size_t)s * C1);
    float* od = g_out1 + (size_t)d * C1;
#pragma unroll
    for (int i = 0; i < 2; i++) {
        int idx = lane + 32 * i;
        float4 v = hs[idx];
        redAdd4(od + idx * 4, make_float4(coef * v.x, coef * v.y, coef * v.z, coef * v.w));
    }
}

__global__ void k_bias_relu1(const float* __restrict__ bc1) {
    int t = blockIdx.x * blockDim.x + threadIdx.x;
    if (t >= NN * (C1 / 4)) return;
    int c4 = t & (C1 / 4 - 1);
    float4 b = ((const float4*)bc1)[c4];
    float4 v = ((float4*)g_out1)[t];
    v.x = fmaxf(v.x + b.x, 0.f);
    v.y = fmaxf(v.y + b.y, 0.f);
    v.z = fmaxf(v.z + b.z, 0.f);
    v.w = fmaxf(v.w + b.w, 0.f);
    ((float4*)g_out1)[t] = v;
}

// m_s / m_d dots over out1, warp per node
__global__ void k_mdots(const float* __restrict__ Wm1) {
    int gw = (blockIdx.x * blockDim.x + threadIdx.x) >> 5;
    int lane = threadIdx.x & 31;
    if (gw >= NN) return;
    const float4* row = (const float4*)(g_out1 + (size_t)gw * C1);
    const float4* wm = (const float4*)Wm1;
    float s = 0.f, d = 0.f;
#pragma unroll
    for (int i = 0; i < 2; i++) {
        int idx = lane + 32 * i;
        float4 v = row[idx];
        float4 ws = wm[idx];
        float4 wd = wm[idx + 64];
        s += v.x * ws.x + v.y * ws.y + v.z * ws.z + v.w * ws.w;
        d += v.x * wd.x + v.y * wd.y + v.z * wd.z + v.w * wd.w;
    }
    s = warpReduceSum(s);
    d = warpReduceSum(d);
    if (lane == 0) { g_ms[gw] = s; g_md[gw] = d; }
}

__global__ void k_edge2(const int* __restrict__ src, const int* __restrict__ dst,
                        const float* __restrict__ bm1) {
    int e = blockIdx.x * blockDim.x + threadIdx.x;
    if (e >= NE) return;
    int s = src[e], d = dst[e];
    float ea = fmaxf(g_ms[s] + g_md[d] + bm1[0], 0.f);
    g_ew2[e] = ea;
    if (ea != 0.f) atomicAdd(&g_deg2[d], ea);
}

__global__ void k_init_out2() {
    int t = blockIdx.x * blockDim.x + threadIdx.x;
    if (t >= NN * (C2 / 4)) return;
    int node = t / (C2 / 4);
    float di = g_deg2[node];
    float c = di * di;
    float4 v = ((const float4*)g_h2)[t];
    ((float4*)g_out2)[t] = make_float4(c * v.x, c * v.y, c * v.z, c * v.w);
}

__global__ void k_scatter2(const int* __restrict__ src, const int* __restrict__ dst) {
    int e = (blockIdx.x * blockDim.x + threadIdx.x) >> 5;
    if (e >= NE) return;
    float ew = g_ew2[e];
    if (ew == 0.f) return;
    int lane = threadIdx.x & 31;
    int s = src[e], d = dst[e];
    float coef = g_deg2[s] * ew * g_deg2[d];
    const float4* hs = (const float4*)(g_h2 + (size_t)s * C2);
    float* od = g_out2 + (size_t)d * C2;
    float4 v = hs[lane];
    redAdd4(od + lane * 4, make_float4(coef * v.x, coef * v.y, coef * v.z, coef * v.w));
}

// proj = out2 @ W_f1  ([N,128]x[128,64]); b_c2 cancels in the pairwise diff so skipped
__global__ void k_proj(const float* __restrict__ Wf1) {
    __shared__ float W1s[C2 * HID];
    for (int i = threadIdx.x; i < C2 * HID; i += blockDim.x) W1s[i] = Wf1[i];
    __syncthreads();
    int t = blockIdx.x * blockDim.x + threadIdx.x;
    int node = t >> 6;
    int j = t & 63;
    if (node >= NN) return;
    const float* row = g_out2 + (size_t)node * C2;
    float acc = 0.f;
#pragma unroll 8
    for (int k = 0; k < C2; k++) acc = fmaf(row[k], W1s[k * HID + j], acc);
    g_proj[(size_t)node * HID + j] = acc;
}

// final: sigmoid( relu(proj[a]-proj[b]+b_f1) @ W_f2 + b_f2 ), warp per edge
__global__ void k_final(const int* __restrict__ ea, const int* __restrict__ eb,
                        const float* __restrict__ bf1, const float* __restrict__ Wf2,
                        const float* __restrict__ bf2, float* __restrict__ out) {
    int e = (blockIdx.x * blockDim.x + threadIdx.x) >> 5;
    if (e >= NE) return;
    int lane = threadIdx.x & 31;
    int a = ea[e], b = eb[e];
    const float* pa = g_proj + (size_t)a * HID;
    const float* pb = g_proj + (size_t)b * HID;
    float acc = 0.f;
#pragma unroll
    for (int i = 0; i < 2; i++) {
        int j = lane + 32 * i;
        float v = fmaxf(pa[j] - pb[j] + bf1[j], 0.f);
        acc = fmaf(v, Wf2[j], acc);
    }
    acc = warpReduceSum(acc);
    if (lane == 0) {
        float z = acc + bf2[0];
        out[e] = 1.f / (1.f + expf(-z));
    }
}

// ---------------- launcher ---------------------------------------------------
extern "C" void kernel_launch(void* const* d_in, const int* in_sizes, int n_in,
                              void* d_out, int out_size) {
    const float* x      = (const float*)d_in[0];
    const float* coords = (const float*)d_in[1];
    const float* W_app  = (const float*)d_in[2];
    const float* b_app  = (const float*)d_in[3];
    const float* W_geom = (const float*)d_in[4];
    const float* b_geom = (const float*)d_in[5];
    const float* W_aff  = (const float*)d_in[6];
    const float* b_aff  = (const float*)d_in[7];
    const float* W_c1   = (const float*)d_in[8];
    const float* b_c1   = (const float*)d_in[9];
    const float* W_m1   = (const float*)d_in[10];
    const float* b_m1   = (const float*)d_in[11];
    const float* W_c2   = (const float*)d_in[12];
    // d_in[13] = b_c2 (cancels in pairwise diff; unused)
    const float* W_f1   = (const float*)d_in[14];
    const float* b_f1   = (const float*)d_in[15];
    const float* W_f2   = (const float*)d_in[16];
    const float* b_f2   = (const float*)d_in[17];
    const int* ei  = (const int*)d_in[18];
    const int* ei2 = (const int*)d_in[19];
    const int* src = ei;
    const int* dst = ei + NE;

    float *h1p, *out1p, *h2p;
    cudaGetSymbolAddress((void**)&h1p, g_h1);
    cudaGetSymbolAddress((void**)&out1p, g_out1);
    cudaGetSymbolAddress((void**)&h2p, g_h2);

    k_zero_deg<<<(NN + 255) / 256, 256>>>();
    k_node_dots<<<(NN + 7) / 8, 256>>>(x, coords, W_app, W_geom);
    k_edge1<<<(NE + 255) / 256, 256>>>(src, dst, W_aff, b_app, b_geom, b_aff);
    k_dinv1<<<(NN + 255) / 256, 256>>>();
    k_gemm_tf32<<<dim3((NN + 127) / 128, C1 / 128), 256>>>(x, W_c1, h1p, NN, C1, DIN);
    k_init_out1<<<(NN * (C1 / 4) + 255) / 256, 256>>>();
    k_scatter1<<<(NE * 32 + 255) / 256, 256>>>(src, dst);
    k_bias_relu1<<<(NN * (C1 / 4) + 255) / 256, 256>>>(b_c1);
    k_mdots<<<(NN + 7) / 8, 256>>>(W_m1);
    k_edge2<<<(NE + 255) / 256, 256>>>(src, dst, b_m1);
    k_dinv2<<<(NN + 255) / 256, 256>>>();
    k_gemm_tf32<<<dim3((NN + 127) / 128, C2 / 128), 256>>>(out1p, W_c2, h2p, NN, C2, C1);
    k_init_out2<<<(NN * (C2 / 4) + 255) / 256, 256>>>();
    k_scatter2<<<(NE * 32 + 255) / 256, 256>>>(src, dst);
    k_proj<<<(NN * HID + 511) / 512, 512>>>(W_f1);
    k_final<<<(NE * 32 + 255) / 256, 256>>>(ei2, ei2 + NE, b_f1, W_f2, b_f2,
                                            (float*)d_out);
}

// round 7
// speedup vs baseline: 1.5516x; 1.0838x over previous
#include <cuda_runtime.h>
#include <cuda_bf16.h>
#include <math.h>
#include <stdint.h>
#include <stddef.h>

// Problem constants (fixed by the dataset)
#define NN 50000
#define NE 800000
#define DIN 512
#define C1 256
#define C2 128
#define HID 64

// ---------------- scratch (device globals; no allocations allowed) ----------
__device__ float g_app_s[NN];
__device__ float g_app_d[NN];
__device__ float g_geo_s[NN];
__device__ float g_geo_d[NN];
__device__ float g_ew1[NE];
__device__ float g_deg1[NN];   // deg, then overwritten with dinv
__device__ float g_ms[NN];
__device__ float g_md[NN];
__device__ float g_ew2[NE];
__device__ float g_deg2[NN];
__device__ float g_h1[(size_t)NN * C1];
__device__ float g_out1[(size_t)NN * C1];   // pre-bias GCN1 accumulator
__device__ float g_h2[(size_t)NN * C2];
__device__ float g_out2[(size_t)NN * C2];
__device__ float g_proj[(size_t)NN * HID];

// ---------------- helpers ----------------------------------------------------
__device__ __forceinline__ void redAdd4(float* addr, float4 v) {
    asm volatile("red.global.add.v4.f32 [%0], {%1,%2,%3,%4};"
                 :: "l"(addr), "f"(v.x), "f"(v.y), "f"(v.z), "f"(v.w)
                 : "memory");
}

__device__ __forceinline__ float warpReduceSum(float v) {
#pragma unroll
    for (int off = 16; off > 0; off >>= 1)
        v += __shfl_down_sync(0xFFFFFFFFu, v, off);
    return v;
}

__device__ __forceinline__ uint32_t f2tf(float f) {
    uint32_t r;
    asm("cvt.rna.tf32.f32 %0, %1;" : "=r"(r) : "f"(f));
    return r;
}

__device__ __forceinline__ void mma_tf32(float* c, const uint32_t* a, const uint32_t* b) {
    asm volatile(
        "mma.sync.aligned.m16n8k8.row.col.f32.tf32.tf32.f32 "
        "{%0,%1,%2,%3}, {%4,%5,%6,%7}, {%8,%9}, {%0,%1,%2,%3};"
        : "+f"(c[0]), "+f"(c[1]), "+f"(c[2]), "+f"(c[3])
        : "r"(a[0]), "r"(a[1]), "r"(a[2]), "r"(a[3]), "r"(b[0]), "r"(b[1]));
}

#define CP_ASYNC16(dst, src) \
    asm volatile("cp.async.cg.shared.global [%0], [%1], 16;" :: "r"(dst), "l"(src))
#define CP_COMMIT asm volatile("cp.async.commit_group;")
template <int N>
__device__ __forceinline__ void cp_wait() {
    asm volatile("cp.async.wait_group %0;" :: "n"(N));
}

// ---------------- kernels ----------------------------------------------------

// node dots + zero both degree accumulators (fused)
__global__ void k_node_dots(const float* __restrict__ x,
                            const float* __restrict__ coords,
                            const float* __restrict__ Wapp,
                            const float* __restrict__ Wgeom) {
    int gw = (blockIdx.x * blockDim.x + threadIdx.x) >> 5;
    int lane = threadIdx.x & 31;
    if (gw >= NN) return;
    const float4* row = (const float4*)(x + (size_t)gw * DIN);
    const float4* wa = (const float4*)Wapp;
    float s = 0.f, d = 0.f;
#pragma unroll
    for (int i = 0; i < 4; i++) {
        int idx = lane + 32 * i;
        float4 v = row[idx];
        float4 ws = wa[idx];
        float4 wd = wa[idx + 128];
        s += v.x * ws.x + v.y * ws.y + v.z * ws.z + v.w * ws.w;
        d += v.x * wd.x + v.y * wd.y + v.z * wd.z + v.w * wd.w;
    }
    s = warpReduceSum(s);
    d = warpReduceSum(d);
    if (lane == 0) {
        g_app_s[gw] = s;
        g_app_d[gw] = d;
        float4 c = ((const float4*)coords)[gw];
        g_geo_s[gw] = c.x * Wgeom[0] + c.y * Wgeom[1] + c.z * Wgeom[2] + c.w * Wgeom[3];
        g_geo_d[gw] = c.x * Wgeom[4] + c.y * Wgeom[5] + c.z * Wgeom[6] + c.w * Wgeom[7];
        g_deg1[gw] = 0.f;
        g_deg2[gw] = 0.f;
    }
}

// edge weights for GCN1 + degree accumulation
__global__ void k_edge1(const int* __restrict__ src, const int* __restrict__ dst,
                        const float* __restrict__ Waff,
                        const float* __restrict__ bapp,
                        const float* __restrict__ bgeom,
                        const float* __restrict__ baff) {
    int e = blockIdx.x * blockDim.x + threadIdx.x;
    if (e >= NE) return;
    int s = src[e], d = dst[e];
    float x1 = fmaxf(g_app_s[s] + g_app_d[d] + bapp[0], 0.f);
    float x2 = fmaxf(g_geo_s[s] + g_geo_d[d] + bgeom[0], 0.f);
    float ew = fmaxf(x1 * Waff[0] + x2 * Waff[1] + baff[0], 0.f);
    g_ew1[e] = ew;
    if (ew != 0.f) atomicAdd(&g_deg1[d], ew);
}

__global__ void k_dinv1() {
    int i = blockIdx.x * blockDim.x + threadIdx.x;
    if (i < NN) g_deg1[i] = rsqrtf(g_deg1[i] + 1.0f);  // +1 self-loop; deg>=1
}

__global__ void k_dinv2() {
    int i = blockIdx.x * blockDim.x + threadIdx.x;
    if (i < NN) g_deg2[i] = rsqrtf(g_deg2[i] + 1.0f);
}

// ---------------- TF32 tensor-core GEMM --------------------------------------
// C[M,N] = A[M,K] @ B[K,N], row-major. Block tile 128x128xBK16, 8 warps,
// warp tile 32x64 via m16n8k8 (2 m-tiles x 8 n-tiles). cp.async double buffer.
// MODE bit0: apply relu(a + biasA[col]) to A fragments (GEMM2 consumes
//            pre-bias GCN1 accumulator).
// MODE bit1: additionally write Cs[r,:] = dinv[r]^2 * C[r,:] (fused self-loop
//            initialization of the GCN accumulator).
// Tail M: A source rows clamped in-bounds; OOB C rows never stored.
#define GA_BM 128
#define GA_BK 16
#define GA_AS_STRIDE 20
#define GA_BS_STRIDE 136

template <int MODE>
__global__ __launch_bounds__(256) void k_gemm_tf32(
    const float* __restrict__ A, const float* __restrict__ B,
    float* __restrict__ C, int M, int N, int K,
    const float* __restrict__ biasA,
    float* __restrict__ Cs, const float* __restrict__ dinv) {
    __shared__ float As[2][GA_BM * GA_AS_STRIDE];
    __shared__ float Bs[2][GA_BK * GA_BS_STRIDE];

    const int tid = threadIdx.x;
    const int lane = tid & 31;
    const int wid = tid >> 5;
    const int wm = wid & 3;       // 0..3  (rows)
    const int wn = wid >> 2;      // 0..1  (cols)
    const int grp = lane >> 2;    // 0..7
    const int qid = lane & 3;     // 0..3

    const int row0 = blockIdx.x * GA_BM;
    const int col0 = blockIdx.y * 128;

    // staging coordinates
    const int ar0 = tid >> 2;               // 0..63
    const int ac = (tid & 3) * 4;           // 0,4,8,12
    const int br0 = tid >> 5;               // 0..7
    const int bc = (tid & 31) * 4;          // 0..124

    // clamped source rows (always in-bounds)
    const int arow_g0 = min(row0 + ar0, M - 1);
    const int arow_g1 = min(row0 + ar0 + 64, M - 1);

    float acc[2][8][4];
#pragma unroll
    for (int mt = 0; mt < 2; mt++)
#pragma unroll
        for (int nt = 0; nt < 8; nt++)
#pragma unroll
            for (int i = 0; i < 4; i++) acc[mt][nt][i] = 0.f;

    auto load_tile = [&](int buf, int k0) {
        uint32_t a_s0 = (uint32_t)__cvta_generic_to_shared(
            &As[buf][ar0 * GA_AS_STRIDE + ac]);
        uint32_t a_s1 = (uint32_t)__cvta_generic_to_shared(
            &As[buf][(ar0 + 64) * GA_AS_STRIDE + ac]);
        const float* a_g0 = A + (size_t)arow_g0 * K + k0 + ac;
        const float* a_g1 = A + (size_t)arow_g1 * K + k0 + ac;
        CP_ASYNC16(a_s0, a_g0);
        CP_ASYNC16(a_s1, a_g1);
        uint32_t b_s0 = (uint32_t)__cvta_generic_to_shared(
            &Bs[buf][br0 * GA_BS_STRIDE + bc]);
        uint32_t b_s1 = (uint32_t)__cvta_generic_to_shared(
            &Bs[buf][(br0 + 8) * GA_BS_STRIDE + bc]);
        const float* b_g0 = B + (size_t)(k0 + br0) * N + col0 + bc;
        const float* b_g1 = B + (size_t)(k0 + br0 + 8) * N + col0 + bc;
        CP_ASYNC16(b_s0, b_g0);
        CP_ASYNC16(b_s1, b_g1);
    };

    const int ntiles = K / GA_BK;
    load_tile(0, 0);
    CP_COMMIT;

    int buf = 0;
    const int arow_base = wm * 32 + grp;
    const int bcol_base = wn * 64 + grp;

    for (int t = 0; t < ntiles; t++) {
        const int k0 = t * GA_BK;
        if (t + 1 < ntiles) {
            load_tile(buf ^ 1, (t + 1) * GA_BK);
            CP_COMMIT;
            cp_wait<1>();
        } else {
            cp_wait<0>();
        }
        __syncthreads();

        const float* as = As[buf];
        const float* bs = Bs[buf];
#pragma unroll
        for (int ks = 0; ks < 2; ks++) {
            const int kk = ks * 8 + qid;
            float ab0 = 0.f, ab1 = 0.f;
            if (MODE & 1) {
                ab0 = biasA[k0 + kk];
                ab1 = biasA[k0 + kk + 4];
            }
            uint32_t a[2][4];
#pragma unroll
            for (int mt = 0; mt < 2; mt++) {
                const float* ap = as + (arow_base + mt * 16) * GA_AS_STRIDE + kk;
                float v0 = ap[0];
                float v1 = ap[8 * GA_AS_STRIDE];
                float v2 = ap[4];
                float v3 = ap[8 * GA_AS_STRIDE + 4];
                if (MODE & 1) {
                    v0 = fmaxf(v0 + ab0, 0.f);
                    v1 = fmaxf(v1 + ab0, 0.f);
                    v2 = fmaxf(v2 + ab1, 0.f);
                    v3 = fmaxf(v3 + ab1, 0.f);
                }
                a[mt][0] = f2tf(v0);
                a[mt][1] = f2tf(v1);
                a[mt][2] = f2tf(v2);
                a[mt][3] = f2tf(v3);
            }
            const float* bp = bs + kk * GA_BS_STRIDE + bcol_base;
#pragma unroll
            for (int nt = 0; nt < 8; nt++) {
                uint32_t b[2];
                b[0] = f2tf(bp[nt * 8]);
                b[1] = f2tf(bp[4 * GA_BS_STRIDE + nt * 8]);
                mma_tf32(acc[0][nt], a[0], b);
                mma_tf32(acc[1][nt], a[1], b);
            }
        }
        __syncthreads();
        buf ^= 1;
    }

    // epilogue: write h (C) and optionally dinv^2-scaled self-loop term (Cs)
#pragma unroll
    for (int mt = 0; mt < 2; mt++) {
        int r = row0 + wm * 32 + mt * 16 + grp;
        float c0 = 0.f, c8 = 0.f;
        if (MODE & 2) {
            if (r < M)     { float d0 = dinv[r];     c0 = d0 * d0; }
            if (r + 8 < M) { float d8 = dinv[r + 8]; c8 = d8 * d8; }
        }
#pragma unroll
        for (int nt = 0; nt < 8; nt++) {
            int c = col0 + wn * 64 + nt * 8 + qid * 2;
            if (r < M) {
                float2 v = make_float2(acc[mt][nt][0], acc[mt][nt][1]);
                *(float2*)(C + (size_t)r * N + c) = v;
                if (MODE & 2) {
                    float2 sv = make_float2(c0 * v.x, c0 * v.y);
                    *(float2*)(Cs + (size_t)r * N + c) = sv;
                }
            }
            if (r + 8 < M) {
                float2 v = make_float2(acc[mt][nt][2], acc[mt][nt][3]);
                *(float2*)(C + (size_t)(r + 8) * N + c) = v;
                if (MODE & 2) {
                    float2 sv = make_float2(c8 * v.x, c8 * v.y);
                    *(float2*)(Cs + (size_t)(r + 8) * N + c) = sv;
                }
            }
        }
    }
}

// per-edge scatter-add (256-dim), warp per edge, float4 red atomics
__global__ void k_scatter1(const int* __restrict__ src, const int* __restrict__ dst) {
    int e = (blockIdx.x * blockDim.x + threadIdx.x) >> 5;
    if (e >= NE) return;
    float ew = g_ew1[e];
    if (ew == 0.f) return;
    int lane = threadIdx.x & 31;
    int s = src[e], d = dst[e];
    float coef = g_deg1[s] * ew * g_deg1[d];
    const float4* hs = (const float4*)(g_h1 + (size_t)s * C1);
    float* od = g_out1 + (size_t)d * C1;
#pragma unroll
    for (int i = 0; i < 2; i++) {
        int idx = lane + 32 * i;
        float4 v = hs[idx];
        redAdd4(od + idx * 4, make_float4(coef * v.x, coef * v.y, coef * v.z, coef * v.w));
    }
}

// m_s / m_d dots over relu(out1 + b_c1), warp per node (bias+relu inline)
__global__ void k_mdots(const float* __restrict__ Wm1, const float* __restrict__ bc1) {
    int gw = (blockIdx.x * blockDim.x + threadIdx.x) >> 5;
    int lane = threadIdx.x & 31;
    if (gw >= NN) return;
    const float4* row = (const float4*)(g_out1 + (size_t)gw * C1);
    const float4* wm = (const float4*)Wm1;
    const float4* bb = (const float4*)bc1;
    float s = 0.f, d = 0.f;
#pragma unroll
    for (int i = 0; i < 2; i++) {
        int idx = lane + 32 * i;
        float4 v = row[idx];
        float4 b = bb[idx];
        v.x = fmaxf(v.x + b.x, 0.f);
        v.y = fmaxf(v.y + b.y, 0.f);
        v.z = fmaxf(v.z + b.z, 0.f);
        v.w = fmaxf(v.w + b.w, 0.f);
        float4 ws = wm[idx];
        float4 wd = wm[idx + 64];
        s += v.x * ws.x + v.y * ws.y + v.z * ws.z + v.w * ws.w;
        d += v.x * wd.x + v.y * wd.y + v.z * wd.z + v.w * wd.w;
    }
    s = warpReduceSum(s);
    d = warpReduceSum(d);
    if (lane == 0) { g_ms[gw] = s; g_md[gw] = d; }
}

__global__ void k_edge2(const int* __restrict__ src, const int* __restrict__ dst,
                        const float* __restrict__ bm1) {
    int e = blockIdx.x * blockDim.x + threadIdx.x;
    if (e >= NE) return;
    int s = src[e], d = dst[e];
    float ea = fmaxf(g_ms[s] + g_md[d] + bm1[0], 0.f);
    g_ew2[e] = ea;
    if (ea != 0.f) atomicAdd(&g_deg2[d], ea);
}

__global__ void k_scatter2(const int* __restrict__ src, const int* __restrict__ dst) {
    int e = (blockIdx.x * blockDim.x + threadIdx.x) >> 5;
    if (e >= NE) return;
    float ew = g_ew2[e];
    if (ew == 0.f) return;
    int lane = threadIdx.x & 31;
    int s = src[e], d = dst[e];
    float coef = g_deg2[s] * ew * g_deg2[d];
    const float4* hs = (const float4*)(g_h2 + (size_t)s * C2);
    float* od = g_out2 + (size_t)d * C2;
    float4 v = hs[lane];
    redAdd4(od + lane * 4, make_float4(coef * v.x, coef * v.y, coef * v.z, coef * v.w));
}

// proj = out2 @ W_f1  ([N,128]x[128,64]); b_c2 cancels in the pairwise diff so skipped
__global__ void k_proj(const float* __restrict__ Wf1) {
    __shared__ float W1s[C2 * HID];
    for (int i = threadIdx.x; i < C2 * HID; i += blockDim.x) W1s[i] = Wf1[i];
    __syncthreads();
    int t = blockIdx.x * blockDim.x + threadIdx.x;
    int node = t >> 6;
    int j = t & 63;
    if (node >= NN) return;
    const float* row = g_out2 + (size_t)node * C2;
    float acc = 0.f;
#pragma unroll 8
    for (int k = 0; k < C2; k++) acc = fmaf(row[k], W1s[k * HID + j], acc);
    g_proj[(size_t)node * HID + j] = acc;
}

// final: sigmoid( relu(proj[a]-proj[b]+b_f1) @ W_f2 + b_f2 )
// half-warp (16 lanes) per edge, float4 loads (16*4 = 64 = HID)
__global__ void k_final(const int* __restrict__ ea, const int* __restrict__ eb,
                        const float* __restrict__ bf1, const float* __restrict__ Wf2,
                        const float* __restrict__ bf2, float* __restrict__ out) {
    int t = blockIdx.x * blockDim.x + threadIdx.x;
    int e = t >> 4;
    if (e >= NE) return;
    int l16 = t & 15;
    int a = ea[e], b = eb[e];
    float4 va = ((const float4*)(g_proj + (size_t)a * HID))[l16];
    float4 vb = ((const float4*)(g_proj + (size_t)b * HID))[l16];
    float4 bb = ((const float4*)bf1)[l16];
    float4 w  = ((const float4*)Wf2)[l16];
    float acc = fmaxf(va.x - vb.x + bb.x, 0.f) * w.x
              + fmaxf(va.y - vb.y + bb.y, 0.f) * w.y
              + fmaxf(va.z - vb.z + bb.z, 0.f) * w.z
              + fmaxf(va.w - vb.w + bb.w, 0.f) * w.w;
#pragma unroll
    for (int off = 8; off > 0; off >>= 1)
        acc += __shfl_down_sync(0xFFFFFFFFu, acc, off, 16);
    if (l16 == 0) {
        float z = acc + bf2[0];
        out[e] = 1.f / (1.f + expf(-z));
    }
}

// ---------------- launcher ---------------------------------------------------
extern "C" void kernel_launch(void* const* d_in, const int* in_sizes, int n_in,
                              void* d_out, int out_size) {
    const float* x      = (const float*)d_in[0];
    const float* coords = (const float*)d_in[1];
    const float* W_app  = (const float*)d_in[2];
    const float* b_app  = (const float*)d_in[3];
    const float* W_geom = (const float*)d_in[4];
    const float* b_geom = (const float*)d_in[5];
    const float* W_aff  = (const float*)d_in[6];
    const float* b_aff  = (const float*)d_in[7];
    const float* W_c1   = (const float*)d_in[8];
    const float* b_c1   = (const float*)d_in[9];
    const float* W_m1   = (const float*)d_in[10];
    const float* b_m1   = (const float*)d_in[11];
    const float* W_c2   = (const float*)d_in[12];
    // d_in[13] = b_c2 (cancels in pairwise diff; unused)
    const float* W_f1   = (const float*)d_in[14];
    const float* b_f1   = (const float*)d_in[15];
    const float* W_f2   = (const float*)d_in[16];
    const float* b_f2   = (const float*)d_in[17];
    const int* ei  = (const int*)d_in[18];
    const int* ei2 = (const int*)d_in[19];
    const int* src = ei;
    const int* dst = ei + NE;

    float *h1p, *out1p, *h2p, *out2p, *dinv1p, *dinv2p;
    cudaGetSymbolAddress((void**)&h1p, g_h1);
    cudaGetSymbolAddress((void**)&out1p, g_out1);
    cudaGetSymbolAddress((void**)&h2p, g_h2);
    cudaGetSymbolAddress((void**)&out2p, g_out2);
    cudaGetSymbolAddress((void**)&dinv1p, g_deg1);
    cudaGetSymbolAddress((void**)&dinv2p, g_deg2);

    // 0
    k_node_dots<<<(NN + 7) / 8, 256>>>(x, coords, W_app, W_geom);
    // 1
    k_edge1<<<(NE + 255) / 256, 256>>>(src, dst, W_aff, b_app, b_geom, b_aff);
    // 2
    k_dinv1<<<(NN + 255) / 256, 256>>>();
    // 3: GEMM1 (h1 = x @ W_c1, + out1 = dinv1^2 * h1)
    k_gemm_tf32<2><<<dim3((NN + 127) / 128, C1 / 128), 256>>>(
        x, W_c1, h1p, NN, C1, DIN, nullptr, out1p, dinv1p);
    // 4
    k_scatter1<<<(NE * 32 + 255) / 256, 256>>>(src, dst);
    // 5
    k_mdots<<<(NN + 7) / 8, 256>>>(W_m1, b_c1);
    // 6
    k_edge2<<<(NE + 255) / 256, 256>>>(src, dst, b_m1);
    // 7
    k_dinv2<<<(NN + 255) / 256, 256>>>();
    // 8: GEMM2 (A = relu(out1 + b_c1) inline, h2 = A @ W_c2, + out2 = dinv2^2 * h2)
    k_gemm_tf32<3><<<dim3((NN + 127) / 128, C2 / 128), 256>>>(
        out1p, W_c2, h2p, NN, C2, C1, b_c1, out2p, dinv2p);
    // 9
    k_scatter2<<<(NE * 32 + 255) / 256, 256>>>(src, dst);
    // 10
    k_proj<<<(NN * HID + 511) / 512, 512>>>(W_f1);
    // 11
    k_final<<<(NE * 16 + 255) / 256, 256>>>(ei2, ei2 + NE, b_f1, W_f2, b_f2,
                                            (float*)d_out);
}

// round 8
// speedup vs baseline: 1.5785x; 1.0173x over previous
#include <cuda_runtime.h>
#include <cuda_bf16.h>
#include <math.h>
#include <stdint.h>
#include <stddef.h>

// Problem constants (fixed by the dataset)
#define NN 50000
#define NE 800000
#define DIN 512
#define C1 256
#define C2 128
#define HID 64

// ---------------- scratch (device globals; no allocations allowed) ----------
__device__ float g_app_s[NN];
__device__ float g_app_d[NN];
__device__ float g_geo_s[NN];
__device__ float g_geo_d[NN];
__device__ float g_ew1[NE];
__device__ float g_deg1[NN];   // deg, then overwritten with dinv
__device__ float g_ms[NN];
__device__ float g_md[NN];
__device__ float g_ew2[NE];
__device__ float g_deg2[NN];
__device__ float g_h1[(size_t)NN * C1];
__device__ float g_out1[(size_t)NN * C1];   // pre-bias GCN1 accumulator
__device__ float g_h2[(size_t)NN * C2];
__device__ float g_out2[(size_t)NN * C2];
__device__ float g_proj[(size_t)NN * HID];

// ---------------- helpers ----------------------------------------------------
__device__ __forceinline__ void redAdd4(float* addr, float4 v) {
    asm volatile("red.global.add.v4.f32 [%0], {%1,%2,%3,%4};"
                 :: "l"(addr), "f"(v.x), "f"(v.y), "f"(v.z), "f"(v.w)
                 : "memory");
}

__device__ __forceinline__ float warpReduceSum(float v) {
#pragma unroll
    for (int off = 16; off > 0; off >>= 1)
        v += __shfl_down_sync(0xFFFFFFFFu, v, off);
    return v;
}

// Raw f32 bits as tf32 operand: HW uses the upper tf32 bits (truncation).
// Doubles operand rounding vs cvt.rna (u 4.9e-4 -> <=9.8e-4) but removes all
// ALU cvt work from the GEMM hot loop. Error budget has >6x margin.
__device__ __forceinline__ uint32_t f2tf(float f) {
    return __float_as_uint(f);
}

__device__ __forceinline__ void mma_tf32(float* c, const uint32_t* a, const uint32_t* b) {
    asm volatile(
        "mma.sync.aligned.m16n8k8.row.col.f32.tf32.tf32.f32 "
        "{%0,%1,%2,%3}, {%4,%5,%6,%7}, {%8,%9}, {%0,%1,%2,%3};"
        : "+f"(c[0]), "+f"(c[1]), "+f"(c[2]), "+f"(c[3])
        : "r"(a[0]), "r"(a[1]), "r"(a[2]), "r"(a[3]), "r"(b[0]), "r"(b[1]));
}

#define CP_ASYNC16(dst, src) \
    asm volatile("cp.async.cg.shared.global [%0], [%1], 16;" :: "r"(dst), "l"(src))
#define CP_COMMIT asm volatile("cp.async.commit_group;")
template <int N>
__device__ __forceinline__ void cp_wait() {
    asm volatile("cp.async.wait_group %0;" :: "n"(N));
}

// ---------------- kernels ----------------------------------------------------

// node dots + zero both degree accumulators (fused)
__global__ void k_node_dots(const float* __restrict__ x,
                            const float* __restrict__ coords,
                            const float* __restrict__ Wapp,
                            const float* __restrict__ Wgeom) {
    int gw = (blockIdx.x * blockDim.x + threadIdx.x) >> 5;
    int lane = threadIdx.x & 31;
    if (gw >= NN) return;
    const float4* row = (const float4*)(x + (size_t)gw * DIN);
    const float4* wa = (const float4*)Wapp;
    float s = 0.f, d = 0.f;
#pragma unroll
    for (int i = 0; i < 4; i++) {
        int idx = lane + 32 * i;
        float4 v = row[idx];
        float4 ws = wa[idx];
        float4 wd = wa[idx + 128];
        s += v.x * ws.x + v.y * ws.y + v.z * ws.z + v.w * ws.w;
        d += v.x * wd.x + v.y * wd.y + v.z * wd.z + v.w * wd.w;
    }
    s = warpReduceSum(s);
    d = warpReduceSum(d);
    if (lane == 0) {
        g_app_s[gw] = s;
        g_app_d[gw] = d;
        float4 c = ((const float4*)coords)[gw];
        g_geo_s[gw] = c.x * Wgeom[0] + c.y * Wgeom[1] + c.z * Wgeom[2] + c.w * Wgeom[3];
        g_geo_d[gw] = c.x * Wgeom[4] + c.y * Wgeom[5] + c.z * Wgeom[6] + c.w * Wgeom[7];
        g_deg1[gw] = 0.f;
        g_deg2[gw] = 0.f;
    }
}

// edge weights for GCN1 + degree accumulation
__global__ void k_edge1(const int* __restrict__ src, const int* __restrict__ dst,
                        const float* __restrict__ Waff,
                        const float* __restrict__ bapp,
                        const float* __restrict__ bgeom,
                        const float* __restrict__ baff) {
    int e = blockIdx.x * blockDim.x + threadIdx.x;
    if (e >= NE) return;
    int s = src[e], d = dst[e];
    float x1 = fmaxf(g_app_s[s] + g_app_d[d] + bapp[0], 0.f);
    float x2 = fmaxf(g_geo_s[s] + g_geo_d[d] + bgeom[0], 0.f);
    float ew = fmaxf(x1 * Waff[0] + x2 * Waff[1] + baff[0], 0.f);
    g_ew1[e] = ew;
    if (ew != 0.f) atomicAdd(&g_deg1[d], ew);
}

__global__ void k_dinv1() {
    int i = blockIdx.x * blockDim.x + threadIdx.x;
    if (i < NN) g_deg1[i] = rsqrtf(g_deg1[i] + 1.0f);  // +1 self-loop; deg>=1
}

__global__ void k_dinv2() {
    int i = blockIdx.x * blockDim.x + threadIdx.x;
    if (i < NN) g_deg2[i] = rsqrtf(g_deg2[i] + 1.0f);
}

// ---------------- TF32 tensor-core GEMM --------------------------------------
// C[M,N] = A[M,K] @ B[K,N], row-major. Block tile 128x128xBK16, 8 warps,
// warp tile 32x64 via m16n8k8 (2 m-tiles x 8 n-tiles). cp.async double buffer.
// MODE bit0: apply relu(a + biasA[col]) to A fragments.
// MODE bit1: additionally write Cs[r,:] = dinv[r]^2 * C[r,:].
// Tail M: A source rows clamped in-bounds; OOB C rows never stored.
#define GA_BM 128
#define GA_BK 16
#define GA_AS_STRIDE 20
#define GA_BS_STRIDE 136

template <int MODE>
__global__ __launch_bounds__(256) void k_gemm_tf32(
    const float* __restrict__ A, const float* __restrict__ B,
    float* __restrict__ C, int M, int N, int K,
    const float* __restrict__ biasA,
    float* __restrict__ Cs, const float* __restrict__ dinv) {
    __shared__ float As[2][GA_BM * GA_AS_STRIDE];
    __shared__ float Bs[2][GA_BK * GA_BS_STRIDE];

    const int tid = threadIdx.x;
    const int lane = tid & 31;
    const int wid = tid >> 5;
    const int wm = wid & 3;       // 0..3  (rows)
    const int wn = wid >> 2;      // 0..1  (cols)
    const int grp = lane >> 2;    // 0..7
    const int qid = lane & 3;     // 0..3

    const int row0 = blockIdx.x * GA_BM;
    const int col0 = blockIdx.y * 128;

    // staging coordinates
    const int ar0 = tid >> 2;               // 0..63
    const int ac = (tid & 3) * 4;           // 0,4,8,12
    const int br0 = tid >> 5;               // 0..7
    const int bc = (tid & 31) * 4;          // 0..124

    // clamped source rows (always in-bounds)
    const int arow_g0 = min(row0 + ar0, M - 1);
    const int arow_g1 = min(row0 + ar0 + 64, M - 1);

    float acc[2][8][4];
#pragma unroll
    for (int mt = 0; mt < 2; mt++)
#pragma unroll
        for (int nt = 0; nt < 8; nt++)
#pragma unroll
            for (int i = 0; i < 4; i++) acc[mt][nt][i] = 0.f;

    auto load_tile = [&](int buf, int k0) {
        uint32_t a_s0 = (uint32_t)__cvta_generic_to_shared(
            &As[buf][ar0 * GA_AS_STRIDE + ac]);
        uint32_t a_s1 = (uint32_t)__cvta_generic_to_shared(
            &As[buf][(ar0 + 64) * GA_AS_STRIDE + ac]);
        const float* a_g0 = A + (size_t)arow_g0 * K + k0 + ac;
        const float* a_g1 = A + (size_t)arow_g1 * K + k0 + ac;
        CP_ASYNC16(a_s0, a_g0);
        CP_ASYNC16(a_s1, a_g1);
        uint32_t b_s0 = (uint32_t)__cvta_generic_to_shared(
            &Bs[buf][br0 * GA_BS_STRIDE + bc]);
        uint32_t b_s1 = (uint32_t)__cvta_generic_to_shared(
            &Bs[buf][(br0 + 8) * GA_BS_STRIDE + bc]);
        const float* b_g0 = B + (size_t)(k0 + br0) * N + col0 + bc;
        const float* b_g1 = B + (size_t)(k0 + br0 + 8) * N + col0 + bc;
        CP_ASYNC16(b_s0, b_g0);
        CP_ASYNC16(b_s1, b_g1);
    };

    const int ntiles = K / GA_BK;
    load_tile(0, 0);
    CP_COMMIT;

    int buf = 0;
    const int arow_base = wm * 32 + grp;
    const int bcol_base = wn * 64 + grp;

    for (int t = 0; t < ntiles; t++) {
        const int k0 = t * GA_BK;
        if (t + 1 < ntiles) {
            load_tile(buf ^ 1, (t + 1) * GA_BK);
            CP_COMMIT;
            cp_wait<1>();
        } else {
            cp_wait<0>();
        }
        __syncthreads();

        const float* as = As[buf];
        const float* bs = Bs[buf];
#pragma unroll
        for (int ks = 0; ks < 2; ks++) {
            const int kk = ks * 8 + qid;
            float ab0 = 0.f, ab1 = 0.f;
            if (MODE & 1) {
                ab0 = biasA[k0 + kk];
                ab1 = biasA[k0 + kk + 4];
            }
            uint32_t a[2][4];
#pragma unroll
            for (int mt = 0; mt < 2; mt++) {
                const float* ap = as + (arow_base + mt * 16) * GA_AS_STRIDE + kk;
                float v0 = ap[0];
                float v1 = ap[8 * GA_AS_STRIDE];
                float v2 = ap[4];
                float v3 = ap[8 * GA_AS_STRIDE + 4];
                if (MODE & 1) {
                    v0 = fmaxf(v0 + ab0, 0.f);
                    v1 = fmaxf(v1 + ab0, 0.f);
                    v2 = fmaxf(v2 + ab1, 0.f);
                    v3 = fmaxf(v3 + ab1, 0.f);
                }
                a[mt][0] = f2tf(v0);
                a[mt][1] = f2tf(v1);
                a[mt][2] = f2tf(v2);
                a[mt][3] = f2tf(v3);
            }
            const float* bp = bs + kk * GA_BS_STRIDE + bcol_base;
#pragma unroll
            for (int nt = 0; nt < 8; nt++) {
                uint32_t b[2];
                b[0] = f2tf(bp[nt * 8]);
                b[1] = f2tf(bp[4 * GA_BS_STRIDE + nt * 8]);
                mma_tf32(acc[0][nt], a[0], b);
                mma_tf32(acc[1][nt], a[1], b);
            }
        }
        __syncthreads();
        buf ^= 1;
    }

    // epilogue: write h (C) and optionally dinv^2-scaled self-loop term (Cs)
#pragma unroll
    for (int mt = 0; mt < 2; mt++) {
        int r = row0 + wm * 32 + mt * 16 + grp;
        float c0 = 0.f, c8 = 0.f;
        if (MODE & 2) {
            if (r < M)     { float d0 = dinv[r];     c0 = d0 * d0; }
            if (r + 8 < M) { float d8 = dinv[r + 8]; c8 = d8 * d8; }
        }
#pragma unroll
        for (int nt = 0; nt < 8; nt++) {
            int c = col0 + wn * 64 + nt * 8 + qid * 2;
            if (r < M) {
                float2 v = make_float2(acc[mt][nt][0], acc[mt][nt][1]);
                *(float2*)(C + (size_t)r * N + c) = v;
                if (MODE & 2) {
                    float2 sv = make_float2(c0 * v.x, c0 * v.y);
                    *(float2*)(Cs + (size_t)r * N + c) = sv;
                }
            }
            if (r + 8 < M) {
                float2 v = make_float2(acc[mt][nt][2], acc[mt][nt][3]);
                *(float2*)(C + (size_t)(r + 8) * N + c) = v;
                if (MODE & 2) {
                    float2 sv = make_float2(c8 * v.x, c8 * v.y);
                    *(float2*)(Cs + (size_t)(r + 8) * N + c) = sv;
                }
            }
        }
    }
}

// per-edge scatter-add (256-dim), warp per edge, float4 red atomics
__global__ void k_scatter1(const int* __restrict__ src, const int* __restrict__ dst) {
    int e = (blockIdx.x * blockDim.x + threadIdx.x) >> 5;
    if (e >= NE) return;
    float ew = g_ew1[e];
    if (ew == 0.f) return;
    int lane = threadIdx.x & 31;
    int s = src[e], d = dst[e];
    float coef = g_deg1[s] * ew * g_deg1[d];
    const float4* hs = (const float4*)(g_h1 + (size_t)s * C1);
    float* od = g_out1 + (size_t)d * C1;
#pragma unroll
    for (int i = 0; i < 2; i++) {
        int idx = lane + 32 * i;
        float4 v = hs[idx];
        redAdd4(od + idx * 4, make_float4(coef * v.x, coef * v.y, coef * v.z, coef * v.w));
    }
}

// m_s / m_d dots over relu(out1 + b_c1), warp per node (bias+relu inline)
__global__ void k_mdots(const float* __restrict__ Wm1, const float* __restrict__ bc1) {
    int gw = (blockIdx.x * blockDim.x + threadIdx.x) >> 5;
    int lane = threadIdx.x & 31;
    if (gw >= NN) return;
    const float4* row = (const float4*)(g_out1 + (size_t)gw * C1);
    const float4* wm = (const float4*)Wm1;
    const float4* bb = (const float4*)bc1;
    float s = 0.f, d = 0.f;
#pragma unroll
    for (int i = 0; i < 2; i++) {
        int idx = lane + 32 * i;
        float4 v = row[idx];
        float4 b = bb[idx];
        v.x = fmaxf(v.x + b.x, 0.f);
        v.y = fmaxf(v.y + b.y, 0.f);
        v.z = fmaxf(v.z + b.z, 0.f);
        v.w = fmaxf(v.w + b.w, 0.f);
        float4 ws = wm[idx];
        float4 wd = wm[idx + 64];
        s += v.x * ws.x + v.y * ws.y + v.z * ws.z + v.w * ws.w;
        d += v.x * wd.x + v.y * wd.y + v.z * wd.z + v.w * wd.w;
    }
    s = warpReduceSum(s);
    d = warpReduceSum(d);
    if (lane == 0) { g_ms[gw] = s; g_md[gw] = d; }
}

__global__ void k_edge2(const int* __restrict__ src, const int* __restrict__ dst,
                        const float* __restrict__ bm1) {
    int e = blockIdx.x * blockDim.x + threadIdx.x;
    if (e >= NE) return;
    int s = src[e], d = dst[e];
    float ea = fmaxf(g_ms[s] + g_md[d] + bm1[0], 0.f);
    g_ew2[e] = ea;
    if (ea != 0.f) atomicAdd(&g_deg2[d], ea);
}

__global__ void k_scatter2(const int* __restrict__ src, const int* __restrict__ dst) {
    int e = (blockIdx.x * blockDim.x + threadIdx.x) >> 5;
    if (e >= NE) return;
    float ew = g_ew2[e];
    if (ew == 0.f) return;
    int lane = threadIdx.x & 31;
    int s = src[e], d = dst[e];
    float coef = g_deg2[s] * ew * g_deg2[d];
    const float4* hs = (const float4*)(g_h2 + (size_t)s * C2);
    float* od = g_out2 + (size_t)d * C2;
    float4 v = hs[lane];
    redAdd4(od + lane * 4, make_float4(coef * v.x, coef * v.y, coef * v.z, coef * v.w));
}

// proj = out2 @ W_f1  ([N,128]x[128,64]); b_c2 cancels in the pairwise diff so skipped
__global__ void k_proj(const float* __restrict__ Wf1) {
    __shared__ float W1s[C2 * HID];
    for (int i = threadIdx.x; i < C2 * HID; i += blockDim.x) W1s[i] = Wf1[i];
    __syncthreads();
    int t = blockIdx.x * blockDim.x + threadIdx.x;
    int node = t >> 6;
    int j = t & 63;
    if (node >= NN) return;
    const float* row = g_out2 + (size_t)node * C2;
    float acc = 0.f;
#pragma unroll 8
    for (int k = 0; k < C2; k++) acc = fmaf(row[k], W1s[k * HID + j], acc);
    g_proj[(size_t)node * HID + j] = acc;
}

// final: sigmoid( relu(proj[a]-proj[b]+b_f1) @ W_f2 + b_f2 )
// half-warp (16 lanes) per edge, float4 loads (16*4 = 64 = HID)
__global__ void k_final(const int* __restrict__ ea, const int* __restrict__ eb,
                        const float* __restrict__ bf1, const float* __restrict__ Wf2,
                        const float* __restrict__ bf2, float* __restrict__ out) {
    int t = blockIdx.x * blockDim.x + threadIdx.x;
    int e = t >> 4;
    if (e >= NE) return;
    int l16 = t & 15;
    int a = ea[e], b = eb[e];
    float4 va = ((const float4*)(g_proj + (size_t)a * HID))[l16];
    float4 vb = ((const float4*)(g_proj + (size_t)b * HID))[l16];
    float4 bb = ((const float4*)bf1)[l16];
    float4 w  = ((const float4*)Wf2)[l16];
    float acc = fmaxf(va.x - vb.x + bb.x, 0.f) * w.x
              + fmaxf(va.y - vb.y + bb.y, 0.f) * w.y
              + fmaxf(va.z - vb.z + bb.z, 0.f) * w.z
              + fmaxf(va.w - vb.w + bb.w, 0.f) * w.w;
#pragma unroll
    for (int off = 8; off > 0; off >>= 1)
        acc += __shfl_down_sync(0xFFFFFFFFu, acc, off, 16);
    if (l16 == 0) {
        float z = acc + bf2[0];
        out[e] = 1.f / (1.f + expf(-z));
    }
}

// ---------------- launcher ---------------------------------------------------
extern "C" void kernel_launch(void* const* d_in, const int* in_sizes, int n_in,
                              void* d_out, int out_size) {
    const float* x      = (const float*)d_in[0];
    const float* coords = (const float*)d_in[1];
    const float* W_app  = (const float*)d_in[2];
    const float* b_app  = (const float*)d_in[3];
    const float* W_geom = (const float*)d_in[4];
    const float* b_geom = (const float*)d_in[5];
    const float* W_aff  = (const float*)d_in[6];
    const float* b_aff  = (const float*)d_in[7];
    const float* W_c1   = (const float*)d_in[8];
    const float* b_c1   = (const float*)d_in[9];
    const float* W_m1   = (const float*)d_in[10];
    const float* b_m1   = (const float*)d_in[11];
    const float* W_c2   = (const float*)d_in[12];
    // d_in[13] = b_c2 (cancels in pairwise diff; unused)
    const float* W_f1   = (const float*)d_in[14];
    const float* b_f1   = (const float*)d_in[15];
    const float* W_f2   = (const float*)d_in[16];
    const float* b_f2   = (const float*)d_in[17];
    const int* ei  = (const int*)d_in[18];
    const int* ei2 = (const int*)d_in[19];
    const int* src = ei;
    const int* dst = ei + NE;

    float *h1p, *out1p, *h2p, *out2p, *dinv1p, *dinv2p;
    cudaGetSymbolAddress((void**)&h1p, g_h1);
    cudaGetSymbolAddress((void**)&out1p, g_out1);
    cudaGetSymbolAddress((void**)&h2p, g_h2);
    cudaGetSymbolAddress((void**)&out2p, g_out2);
    cudaGetSymbolAddress((void**)&dinv1p, g_deg1);
    cudaGetSymbolAddress((void**)&dinv2p, g_deg2);

    // 0
    k_node_dots<<<(NN + 7) / 8, 256>>>(x, coords, W_app, W_geom);
    // 1
    k_edge1<<<(NE + 255) / 256, 256>>>(src, dst, W_aff, b_app, b_geom, b_aff);
    // 2
    k_dinv1<<<(NN + 255) / 256, 256>>>();
    // 3: GEMM1 (h1 = x @ W_c1, + out1 = dinv1^2 * h1)
    k_gemm_tf32<2><<<dim3((NN + 127) / 128, C1 / 128), 256>>>(
        x, W_c1, h1p, NN, C1, DIN, nullptr, out1p, dinv1p);
    // 4
    k_scatter1<<<(NE * 32 + 255) / 256, 256>>>(src, dst);
    // 5
    k_mdots<<<(NN + 7) / 8, 256>>>(W_m1, b_c1);
    // 6
    k_edge2<<<(NE + 255) / 256, 256>>>(src, dst, b_m1);
    // 7
    k_dinv2<<<(NN + 255) / 256, 256>>>();
    // 8: GEMM2 (A = relu(out1 + b_c1) inline, h2 = A @ W_c2, + out2 = dinv2^2 * h2)
    k_gemm_tf32<3><<<dim3((NN + 127) / 128, C2 / 128), 256>>>(
        out1p, W_c2, h2p, NN, C2, C1, b_c1, out2p, dinv2p);
    // 9
    k_scatter2<<<(NE * 32 + 255) / 256, 256>>>(src, dst);
    // 10
    k_proj<<<(NN * HID + 511) / 512, 512>>>(W_f1);
    // 11
    k_final<<<(NE * 16 + 255) / 256, 256>>>(ei2, ei2 + NE, b_f1, W_f2, b_f2,
                                            (float*)d_out);
}